// round 7
// baseline (speedup 1.0000x reference)
#include <cuda_runtime.h>
#include <math.h>
#include <stdint.h>

#define L_SEQ  2048
#define NB     4
#define EMB    768
#define NHEAD  12
#define DH     64
#define ROWS   (L_SEQ * NB)      // 8192
#define E3     (3 * EMB)         // 2304
#define E4     (4 * EMB)         // 3072

// ---------------- scratch ----------------
__device__ float g_h   [ (size_t)ROWS * EMB ];
__device__ float g_qkv [ (size_t)ROWS * E3  ];
__device__ float g_attn[ (size_t)ROWS * EMB ];
__device__ float g_x1  [ (size_t)ROWS * EMB ];
__device__ float g_f   [ (size_t)ROWS * E4  ];

#define CVT_TF32(d, s) asm volatile("cvt.rna.tf32.f32 %0, %1;" : "=r"(d) : "f"(s))

__device__ __forceinline__ float ex2f(float x) {
    float y; asm("ex2.approx.f32 %0, %1;" : "=f"(y) : "f"(x)); return y;
}
__device__ __forceinline__ void mma8(float* c, const uint32_t* a, uint32_t b0, uint32_t b1) {
    asm volatile(
        "mma.sync.aligned.m16n8k8.row.col.f32.tf32.tf32.f32 "
        "{%0,%1,%2,%3}, {%4,%5,%6,%7}, {%8,%9}, {%0,%1,%2,%3};"
        : "+f"(c[0]), "+f"(c[1]), "+f"(c[2]), "+f"(c[3])
        : "r"(a[0]), "r"(a[1]), "r"(a[2]), "r"(a[3]), "r"(b0), "r"(b1));
}

// ---------------- LayerNorm ----------------
__global__ __launch_bounds__(256) void ln_kernel(const float* __restrict__ x,
                                                 const float* __restrict__ w,
                                                 const float* __restrict__ b,
                                                 float* __restrict__ out)
{
    int row = blockIdx.x;
    const float* xr = x + (size_t)row * EMB;
    float* orow = out + (size_t)row * EMB;
    int t = threadIdx.x;

    float v[3];
    float sum = 0.f, sq = 0.f;
#pragma unroll
    for (int i = 0; i < 3; i++) {
        v[i] = xr[t + 256 * i];
        sum += v[i];
        sq  += v[i] * v[i];
    }
    __shared__ float s1[8], s2[8], bc[2];
    for (int o = 16; o > 0; o >>= 1) {
        sum += __shfl_xor_sync(0xffffffffu, sum, o);
        sq  += __shfl_xor_sync(0xffffffffu, sq,  o);
    }
    int wid = t >> 5, lid = t & 31;
    if (lid == 0) { s1[wid] = sum; s2[wid] = sq; }
    __syncthreads();
    if (t == 0) {
        float ts = 0.f, tq = 0.f;
#pragma unroll
        for (int i = 0; i < 8; i++) { ts += s1[i]; tq += s2[i]; }
        float mu  = ts * (1.0f / EMB);
        float var = tq * (1.0f / EMB) - mu * mu;
        bc[0] = mu;
        bc[1] = rsqrtf(var + 1e-5f);
    }
    __syncthreads();
    float mu = bc[0], rstd = bc[1];
#pragma unroll
    for (int i = 0; i < 3; i++) {
        int c = t + 256 * i;
        orow[c] = (v[i] - mu) * rstd * w[c] + b[c];
    }
}

// ---------------- explicit-mma tf32 GEMM: C = A[M,K] @ B[N,K]^T + bias (+EPI) ----------------
// 128x128x16 tile, 256 threads, 8 warps (2x4), 64x32 warp tile = 4x4 m16n8k8 frags.
// Smem [m][k] / [n][k] with stride 20 -> conflict-free LDS.32 fragment fetches.
#define GSTR 20
#define GBUF (128 * GSTR)            // floats per operand buffer
#define GT_SMEM (4 * GBUF * 4)       // 2 ops x 2 buffers x 4B = 40960

template <int EPI>
__global__ __launch_bounds__(256) void gemm_mma(
    const float* __restrict__ A, const float* __restrict__ B,
    const float* __restrict__ bias, const float* __restrict__ res,
    float* __restrict__ C, int M, int N, int K)
{
    extern __shared__ float smem[];
    float* As = smem;                // [2][128][GSTR]
    float* Bs = smem + 2 * GBUF;     // [2][128][GSTR]

    const int tid  = threadIdx.x;
    const int wid  = tid >> 5;
    const int lane = tid & 31;
    const int g = lane >> 2, t = lane & 3;

    const int bm = blockIdx.y * 128;
    const int bn = blockIdx.x * 128;
    const int wm = (wid >> 2) * 64;      // warp row offset
    const int wn = (wid & 3) * 32;       // warp col offset

    // staging: each thread loads 8 floats of A and 8 of B per chunk
    const int lr = tid >> 1;             // 0..127
    const int lk = (tid & 1) * 8;        // 0 or 8
    const float* Ap = A + (size_t)(bm + lr) * K + lk;
    const float* Bp = B + (size_t)(bn + lr) * K + lk;
    uint32_t* const stA = (uint32_t*)&As[lr * GSTR + lk];
    uint32_t* const stB = (uint32_t*)&Bs[lr * GSTR + lk];

    float acc[4][4][4];                  // [mt][nt][frag]
#pragma unroll
    for (int i = 0; i < 4; i++)
#pragma unroll
        for (int j = 0; j < 4; j++)
#pragma unroll
            for (int q = 0; q < 4; q++) acc[i][j][q] = 0.f;

    // preload chunk 0 -> buffer 0
    {
        float4 a0 = *(const float4*)(Ap);
        float4 a1 = *(const float4*)(Ap + 4);
        float4 b0 = *(const float4*)(Bp);
        float4 b1 = *(const float4*)(Bp + 4);
        CVT_TF32(stA[0], a0.x); CVT_TF32(stA[1], a0.y); CVT_TF32(stA[2], a0.z); CVT_TF32(stA[3], a0.w);
        CVT_TF32(stA[4], a1.x); CVT_TF32(stA[5], a1.y); CVT_TF32(stA[6], a1.z); CVT_TF32(stA[7], a1.w);
        CVT_TF32(stB[0], b0.x); CVT_TF32(stB[1], b0.y); CVT_TF32(stB[2], b0.z); CVT_TF32(stB[3], b0.w);
        CVT_TF32(stB[4], b1.x); CVT_TF32(stB[5], b1.y); CVT_TF32(stB[6], b1.z); CVT_TF32(stB[7], b1.w);
    }
    __syncthreads();

    const int NC = K / 16;
    for (int c = 0; c < NC; c++) {
        const int s = c & 1;
        float4 a0, a1, b0, b1;
        const bool more = (c + 1 < NC);
        if (more) {
            const float* Apc = Ap + (size_t)(c + 1) * 16;
            const float* Bpc = Bp + (size_t)(c + 1) * 16;
            a0 = *(const float4*)(Apc);
            a1 = *(const float4*)(Apc + 4);
            b0 = *(const float4*)(Bpc);
            b1 = *(const float4*)(Bpc + 4);
        }

        const uint32_t* Asb = (const uint32_t*)(As + s * GBUF);
        const uint32_t* Bsb = (const uint32_t*)(Bs + s * GBUF);
#pragma unroll
        for (int kk = 0; kk < 16; kk += 8) {
            uint32_t af[4][4];
#pragma unroll
            for (int mt = 0; mt < 4; mt++) {
                int r0 = (wm + mt * 16 + g) * GSTR + kk + t;
                af[mt][0] = Asb[r0];
                af[mt][1] = Asb[r0 + 8 * GSTR];
                af[mt][2] = Asb[r0 + 4];
                af[mt][3] = Asb[r0 + 8 * GSTR + 4];
            }
#pragma unroll
            for (int nt = 0; nt < 4; nt++) {
                int rb = (wn + nt * 8 + g) * GSTR + kk + t;
                uint32_t bf0 = Bsb[rb];
                uint32_t bf1 = Bsb[rb + 4];
#pragma unroll
                for (int mt = 0; mt < 4; mt++)
                    mma8(acc[mt][nt], af[mt], bf0, bf1);
            }
        }

        if (more) {
            __syncthreads();   // all warps done reading buffer s^1 from prior iter
            uint32_t* dA = stA + (s ^ 1) * GBUF;
            uint32_t* dB = stB + (s ^ 1) * GBUF;
            CVT_TF32(dA[0], a0.x); CVT_TF32(dA[1], a0.y); CVT_TF32(dA[2], a0.z); CVT_TF32(dA[3], a0.w);
            CVT_TF32(dA[4], a1.x); CVT_TF32(dA[5], a1.y); CVT_TF32(dA[6], a1.z); CVT_TF32(dA[7], a1.w);
            CVT_TF32(dB[0], b0.x); CVT_TF32(dB[1], b0.y); CVT_TF32(dB[2], b0.z); CVT_TF32(dB[3], b0.w);
            CVT_TF32(dB[4], b1.x); CVT_TF32(dB[5], b1.y); CVT_TF32(dB[6], b1.z); CVT_TF32(dB[7], b1.w);
            __syncthreads();
        }
    }

    // ---- epilogue: direct fragment stores (cols 2t, 2t+1 -> float2) ----
#pragma unroll
    for (int mt = 0; mt < 4; mt++) {
#pragma unroll
        for (int nt = 0; nt < 4; nt++) {
            int gcol = bn + wn + nt * 8 + 2 * t;
            float2 bv = *(const float2*)&bias[gcol];
            int r0 = bm + wm + mt * 16 + g;
#pragma unroll
            for (int hrow = 0; hrow < 2; hrow++) {
                size_t gidx = (size_t)(r0 + hrow * 8) * N + gcol;
                float c0 = acc[mt][nt][2 * hrow]     + bv.x;
                float c1 = acc[mt][nt][2 * hrow + 1] + bv.y;
                if (EPI == 1) {
                    float2 rv = *(const float2*)&res[gidx];
                    c0 += rv.x; c1 += rv.y;
                }
                if (EPI == 2) {
                    c0 = c0 / (1.f + __expf(-1.702f * c0));
                    c1 = c1 / (1.f + __expf(-1.702f * c1));
                }
                *(float2*)&C[gidx] = make_float2(c0, c1);
            }
        }
    }
}

// ---------------- Flash attention via mma.sync tf32 (unchanged from R6) ----------------
#define KS_STR 68
#define VS_STR 72
#define PS_STR 68
#define ATT_SMEM ((64 * KS_STR + 64 * VS_STR + 4 * 16 * PS_STR) * 4)

__global__ __launch_bounds__(128) void attn_mma(const float* __restrict__ qkv,
                                                float* __restrict__ o)
{
    extern __shared__ float asmem[];
    float* Ks = asmem;
    float* Vs = asmem + 64 * KS_STR;
    float* Ps = asmem + 64 * KS_STR + 64 * VS_STR;

    const int tid  = threadIdx.x;
    const int w    = tid >> 5;
    const int lane = tid & 31;
    const int g = lane >> 2, t = lane & 3;
    const int qb = blockIdx.x * 64 + w * 16;
    const int h = blockIdx.y, n = blockIdx.z;

    const float qscale = 0.125f * 1.44269504088896f;

    uint32_t aq[8][4];
    {
        size_t r0 = ((size_t)(qb + g) * NB + n) * E3 + h * DH;
        size_t r1 = ((size_t)(qb + g + 8) * NB + n) * E3 + h * DH;
#pragma unroll
        for (int ch = 0; ch < 8; ch++) {
            float v0 = qkv[r0 + ch * 8 + t]     * qscale;
            float v1 = qkv[r1 + ch * 8 + t]     * qscale;
            float v2 = qkv[r0 + ch * 8 + t + 4] * qscale;
            float v3 = qkv[r1 + ch * 8 + t + 4] * qscale;
            CVT_TF32(aq[ch][0], v0); CVT_TF32(aq[ch][1], v1);
            CVT_TF32(aq[ch][2], v2); CVT_TF32(aq[ch][3], v3);
        }
    }

    float oc[8][4];
#pragma unroll
    for (int i = 0; i < 8; i++)
#pragma unroll
        for (int j = 0; j < 4; j++) oc[i][j] = 0.f;
    float m0 = -1e30f, m1 = -1e30f, l0 = 0.f, l1 = 0.f;

    const int srow  = tid >> 1;
    const int shalf = (tid & 1) * 32;

    for (int kb = 0; kb < L_SEQ / 64; kb++) {
        size_t kbase = ((size_t)(kb * 64 + srow) * NB + n) * E3 + EMB + h * DH + shalf;
        float4 kr[8];
#pragma unroll
        for (int i = 0; i < 8; i++) kr[i] = *(const float4*)&qkv[kbase + 4 * i];
        __syncthreads();
        {
            uint32_t* ks = (uint32_t*)&Ks[srow * KS_STR + shalf];
#pragma unroll
            for (int i = 0; i < 8; i++) {
                uint4 cv;
                CVT_TF32(cv.x, kr[i].x); CVT_TF32(cv.y, kr[i].y);
                CVT_TF32(cv.z, kr[i].z); CVT_TF32(cv.w, kr[i].w);
                *(uint4*)&ks[4 * i] = cv;
            }
        }
        size_t vbase = kbase + EMB;
#pragma unroll
        for (int i = 0; i < 8; i++) kr[i] = *(const float4*)&qkv[vbase + 4 * i];
        {
            uint32_t* vs = (uint32_t*)&Vs[srow * VS_STR + shalf];
#pragma unroll
            for (int i = 0; i < 8; i++) {
                uint4 cv;
                CVT_TF32(cv.x, kr[i].x); CVT_TF32(cv.y, kr[i].y);
                CVT_TF32(cv.z, kr[i].z); CVT_TF32(cv.w, kr[i].w);
                *(uint4*)&vs[4 * i] = cv;
            }
        }
        __syncthreads();

        float sc[8][4];
#pragma unroll
        for (int i = 0; i < 8; i++)
#pragma unroll
            for (int j = 0; j < 4; j++) sc[i][j] = 0.f;

        const uint32_t* ksb = (const uint32_t*)Ks;
#pragma unroll
        for (int nt = 0; nt < 8; nt++) {
#pragma unroll
            for (int ch = 0; ch < 8; ch++) {
                uint32_t b0 = ksb[(nt * 8 + g) * KS_STR + ch * 8 + t];
                uint32_t b1 = ksb[(nt * 8 + g) * KS_STR + ch * 8 + t + 4];
                mma8(sc[nt], aq[ch], b0, b1);
            }
        }

        float tm0 = -1e30f, tm1 = -1e30f;
#pragma unroll
        for (int nt = 0; nt < 8; nt++) {
            tm0 = fmaxf(tm0, fmaxf(sc[nt][0], sc[nt][1]));
            tm1 = fmaxf(tm1, fmaxf(sc[nt][2], sc[nt][3]));
        }
        tm0 = fmaxf(tm0, __shfl_xor_sync(0xffffffffu, tm0, 1));
        tm0 = fmaxf(tm0, __shfl_xor_sync(0xffffffffu, tm0, 2));
        tm1 = fmaxf(tm1, __shfl_xor_sync(0xffffffffu, tm1, 1));
        tm1 = fmaxf(tm1, __shfl_xor_sync(0xffffffffu, tm1, 2));

        float nm0 = fmaxf(m0, tm0), nm1 = fmaxf(m1, tm1);
        float al0 = ex2f(m0 - nm0), al1 = ex2f(m1 - nm1);
        m0 = nm0; m1 = nm1;

        float s0 = 0.f, s1 = 0.f;
#pragma unroll
        for (int nt = 0; nt < 8; nt++) {
            sc[nt][0] = ex2f(sc[nt][0] - m0);
            sc[nt][1] = ex2f(sc[nt][1] - m0);
            sc[nt][2] = ex2f(sc[nt][2] - m1);
            sc[nt][3] = ex2f(sc[nt][3] - m1);
            s0 += sc[nt][0] + sc[nt][1];
            s1 += sc[nt][2] + sc[nt][3];
        }
        s0 += __shfl_xor_sync(0xffffffffu, s0, 1);
        s0 += __shfl_xor_sync(0xffffffffu, s0, 2);
        s1 += __shfl_xor_sync(0xffffffffu, s1, 1);
        s1 += __shfl_xor_sync(0xffffffffu, s1, 2);
        l0 = l0 * al0 + s0;
        l1 = l1 * al1 + s1;
#pragma unroll
        for (int nt = 0; nt < 8; nt++) {
            oc[nt][0] *= al0; oc[nt][1] *= al0;
            oc[nt][2] *= al1; oc[nt][3] *= al1;
        }

        uint32_t* pw = (uint32_t*)(Ps + w * 16 * PS_STR);
        __syncwarp();
#pragma unroll
        for (int nt = 0; nt < 8; nt++) {
            uint2 p0, p1;
            CVT_TF32(p0.x, sc[nt][0]); CVT_TF32(p0.y, sc[nt][1]);
            CVT_TF32(p1.x, sc[nt][2]); CVT_TF32(p1.y, sc[nt][3]);
            *(uint2*)&pw[g * PS_STR + nt * 8 + 2 * t]       = p0;
            *(uint2*)&pw[(g + 8) * PS_STR + nt * 8 + 2 * t] = p1;
        }
        __syncwarp();

        const uint32_t* vsb = (const uint32_t*)Vs;
#pragma unroll
        for (int ch = 0; ch < 8; ch++) {
            uint32_t ap[4];
            ap[0] = pw[g * PS_STR + ch * 8 + t];
            ap[1] = pw[(g + 8) * PS_STR + ch * 8 + t];
            ap[2] = pw[g * PS_STR + ch * 8 + t + 4];
            ap[3] = pw[(g + 8) * PS_STR + ch * 8 + t + 4];
#pragma unroll
            for (int nt = 0; nt < 8; nt++) {
                uint32_t b0 = vsb[(ch * 8 + t) * VS_STR + nt * 8 + g];
                uint32_t b1 = vsb[(ch * 8 + t + 4) * VS_STR + nt * 8 + g];
                mma8(oc[nt], ap, b0, b1);
            }
        }
    }

    float i0 = 1.f / l0, i1 = 1.f / l1;
    size_t o0 = ((size_t)(qb + g) * NB + n) * EMB + h * DH;
    size_t o1 = ((size_t)(qb + g + 8) * NB + n) * EMB + h * DH;
#pragma unroll
    for (int nt = 0; nt < 8; nt++) {
        *(float2*)&o[o0 + nt * 8 + 2 * t] = make_float2(oc[nt][0] * i0, oc[nt][1] * i0);
        *(float2*)&o[o1 + nt * 8 + 2 * t] = make_float2(oc[nt][2] * i1, oc[nt][3] * i1);
    }
}

// ---------------- launch ----------------
extern "C" void kernel_launch(void* const* d_in, const int* in_sizes, int n_in,
                              void* d_out, int out_size)
{
    const float* x      = (const float*)d_in[0];
    const float* ln1_w  = (const float*)d_in[1];
    const float* ln1_b  = (const float*)d_in[2];
    const float* w_qkv  = (const float*)d_in[3];
    const float* b_qkv  = (const float*)d_in[4];
    const float* w_out  = (const float*)d_in[5];
    const float* b_out  = (const float*)d_in[6];
    const float* ln2_w  = (const float*)d_in[7];
    const float* ln2_b  = (const float*)d_in[8];
    const float* w_fc   = (const float*)d_in[9];
    const float* b_fc   = (const float*)d_in[10];
    const float* w_proj = (const float*)d_in[11];
    const float* b_proj = (const float*)d_in[12];
    float* out = (float*)d_out;

    float *h, *qkv, *attn, *x1, *f;
    cudaGetSymbolAddress((void**)&h,    g_h);
    cudaGetSymbolAddress((void**)&qkv,  g_qkv);
    cudaGetSymbolAddress((void**)&attn, g_attn);
    cudaGetSymbolAddress((void**)&x1,   g_x1);
    cudaGetSymbolAddress((void**)&f,    g_f);

    cudaFuncSetAttribute(gemm_mma<0>, cudaFuncAttributeMaxDynamicSharedMemorySize, GT_SMEM);
    cudaFuncSetAttribute(gemm_mma<1>, cudaFuncAttributeMaxDynamicSharedMemorySize, GT_SMEM);
    cudaFuncSetAttribute(gemm_mma<2>, cudaFuncAttributeMaxDynamicSharedMemorySize, GT_SMEM);
    cudaFuncSetAttribute(attn_mma,    cudaFuncAttributeMaxDynamicSharedMemorySize, ATT_SMEM);

    ln_kernel<<<ROWS, 256>>>(x, ln1_w, ln1_b, h);
    gemm_mma<0><<<dim3(E3 / 128, ROWS / 128), 256, GT_SMEM>>>(h, w_qkv, b_qkv, nullptr, qkv,
                                                              ROWS, E3, EMB);
    attn_mma<<<dim3(L_SEQ / 64, NHEAD, NB), 128, ATT_SMEM>>>(qkv, attn);
    gemm_mma<1><<<dim3(EMB / 128, ROWS / 128), 256, GT_SMEM>>>(attn, w_out, b_out, x, x1,
                                                               ROWS, EMB, EMB);
    ln_kernel<<<ROWS, 256>>>(x1, ln2_w, ln2_b, h);
    gemm_mma<2><<<dim3(E4 / 128, ROWS / 128), 256, GT_SMEM>>>(h, w_fc, b_fc, nullptr, f,
                                                              ROWS, E4, EMB);
    gemm_mma<1><<<dim3(EMB / 128, ROWS / 128), 256, GT_SMEM>>>(f, w_proj, b_proj, x1, out,
                                                               ROWS, EMB, E4);
}

// round 8
// speedup vs baseline: 1.5764x; 1.5764x over previous
#include <cuda_runtime.h>
#include <math.h>
#include <stdint.h>

#define L_SEQ  2048
#define NB     4
#define EMB    768
#define NHEAD  12
#define DH     64
#define ROWS   (L_SEQ * NB)      // 8192
#define E3     (3 * EMB)         // 2304
#define E4     (4 * EMB)         // 3072

// ---------------- scratch ----------------
__device__ float g_h   [ (size_t)ROWS * EMB ];
__device__ float g_qkv [ (size_t)ROWS * E3  ];
__device__ float g_attn[ (size_t)ROWS * EMB ];
__device__ float g_x1  [ (size_t)ROWS * EMB ];
__device__ float g_f   [ (size_t)ROWS * E4  ];

#define CVT_TF32(d, s) asm volatile("cvt.rna.tf32.f32 %0, %1;" : "=r"(d) : "f"(s))

__device__ __forceinline__ float ex2f(float x) {
    float y; asm("ex2.approx.f32 %0, %1;" : "=f"(y) : "f"(x)); return y;
}
__device__ __forceinline__ void mma8v(float* c,
                                      uint32_t a0, uint32_t a1, uint32_t a2, uint32_t a3,
                                      uint32_t b0, uint32_t b1) {
    asm volatile(
        "mma.sync.aligned.m16n8k8.row.col.f32.tf32.tf32.f32 "
        "{%0,%1,%2,%3}, {%4,%5,%6,%7}, {%8,%9}, {%0,%1,%2,%3};"
        : "+f"(c[0]), "+f"(c[1]), "+f"(c[2]), "+f"(c[3])
        : "r"(a0), "r"(a1), "r"(a2), "r"(a3), "r"(b0), "r"(b1));
}

// ---------------- LayerNorm ----------------
__global__ __launch_bounds__(256) void ln_kernel(const float* __restrict__ x,
                                                 const float* __restrict__ w,
                                                 const float* __restrict__ b,
                                                 float* __restrict__ out)
{
    int row = blockIdx.x;
    const float* xr = x + (size_t)row * EMB;
    float* orow = out + (size_t)row * EMB;
    int t = threadIdx.x;

    float v[3];
    float sum = 0.f, sq = 0.f;
#pragma unroll
    for (int i = 0; i < 3; i++) {
        v[i] = xr[t + 256 * i];
        sum += v[i];
        sq  += v[i] * v[i];
    }
    __shared__ float s1[8], s2[8], bc[2];
    for (int o = 16; o > 0; o >>= 1) {
        sum += __shfl_xor_sync(0xffffffffu, sum, o);
        sq  += __shfl_xor_sync(0xffffffffu, sq,  o);
    }
    int wid = t >> 5, lid = t & 31;
    if (lid == 0) { s1[wid] = sum; s2[wid] = sq; }
    __syncthreads();
    if (t == 0) {
        float ts = 0.f, tq = 0.f;
#pragma unroll
        for (int i = 0; i < 8; i++) { ts += s1[i]; tq += s2[i]; }
        float mu  = ts * (1.0f / EMB);
        float var = tq * (1.0f / EMB) - mu * mu;
        bc[0] = mu;
        bc[1] = rsqrtf(var + 1e-5f);
    }
    __syncthreads();
    float mu = bc[0], rstd = bc[1];
#pragma unroll
    for (int i = 0; i < 3; i++) {
        int c = t + 256 * i;
        orow[c] = (v[i] - mu) * rstd * w[c] + b[c];
    }
}

// ---------------- explicit-mma tf32 GEMM, k-permuted swizzled smem ----------------
// C = A[M,K] @ B[N,K]^T + bias (+EPI). 128x128x16 tile, 256 thr, 8 warps 2x4.
// Smem word k of row r lives at col perm(k)^sw(r): perm(k)=(k&3)*4+(k>>2),
// sw(r)=((r&3)^((r>>2)&3))*4, row stride 16 -> whole k16 fragment = 1 LDS.128.
#define GBUF (128 * 16)              // floats per operand buffer (8KB)
#define GT_SMEM (4 * GBUF * 4)       // 32768 bytes

template <int EPI>
__global__ __launch_bounds__(256, 2) void gemm_mma(
    const float* __restrict__ A, const float* __restrict__ B,
    const float* __restrict__ bias, const float* __restrict__ res,
    float* __restrict__ C, int M, int N, int K)
{
    extern __shared__ float smem[];
    float* As = smem;                // [2][128][16]
    float* Bs = smem + 2 * GBUF;

    const int tid  = threadIdx.x;
    const int wid  = tid >> 5;
    const int lane = tid & 31;
    const int g = lane >> 2, t = lane & 3;

    const int bm = blockIdx.y * 128;
    const int bn = blockIdx.x * 128;
    const int wm = (wid >> 2) * 64;
    const int wn = (wid & 3) * 32;

    // ---- staging setup ----
    const int lr = tid >> 1;             // 0..127
    const int lk = (tid & 1) * 8;        // 0 or 8
    const float* Ap = A + (size_t)(bm + lr) * K + lk;
    const float* Bp = B + (size_t)(bn + lr) * K + lk;
    const int sw_st = ((lr & 3) ^ ((lr >> 2) & 3)) << 2;
    int col[8];
#pragma unroll
    for (int i = 0; i < 8; i++) {
        int k = lk + i;
        col[i] = (((k & 3) << 2) | (k >> 2)) ^ sw_st;
    }
    uint32_t* const stA = (uint32_t*)&As[lr * 16];
    uint32_t* const stB = (uint32_t*)&Bs[lr * 16];

    // ---- read setup ----
    const int cA0 = (4 * t) ^ (((g & 3) ^ ((g >> 2) & 3)) << 2);          // rows = g mod 16
    const int cA8 = (4 * t) ^ (((g & 3) ^ (((g >> 2) + 2) & 3)) << 2);    // rows = g+8 mod 16
    int cB[4];
#pragma unroll
    for (int nt = 0; nt < 4; nt++)
        cB[nt] = (4 * t) ^ (((g & 3) ^ (((g >> 2) + 2 * nt) & 3)) << 2);

    float acc[4][4][4];
#pragma unroll
    for (int i = 0; i < 4; i++)
#pragma unroll
        for (int j = 0; j < 4; j++)
#pragma unroll
            for (int q = 0; q < 4; q++) acc[i][j][q] = 0.f;

    // ---- preload chunk 0 into buffer 0 ----
    {
        float4 a0 = *(const float4*)(Ap);
        float4 a1 = *(const float4*)(Ap + 4);
        float4 b0 = *(const float4*)(Bp);
        float4 b1 = *(const float4*)(Bp + 4);
        float av[8] = {a0.x, a0.y, a0.z, a0.w, a1.x, a1.y, a1.z, a1.w};
        float bv[8] = {b0.x, b0.y, b0.z, b0.w, b1.x, b1.y, b1.z, b1.w};
#pragma unroll
        for (int i = 0; i < 8; i++) {
            uint32_t ua, ub;
            CVT_TF32(ua, av[i]); CVT_TF32(ub, bv[i]);
            stA[col[i]] = ua; stB[col[i]] = ub;
        }
    }
    __syncthreads();

    const int NC = K / 16;
    for (int c = 0; c < NC; c++) {
        const int s = c & 1;
        const bool more = (c + 1 < NC);
        float4 pa0, pa1, pb0, pb1;
        if (more) {
            const float* Apc = Ap + (size_t)(c + 1) * 16;
            const float* Bpc = Bp + (size_t)(c + 1) * 16;
            pa0 = *(const float4*)(Apc);
            pa1 = *(const float4*)(Apc + 4);
            pb0 = *(const float4*)(Bpc);
            pb1 = *(const float4*)(Bpc + 4);
        }

        const uint32_t* Ab = (const uint32_t*)(As + s * GBUF);
        const uint32_t* Bb = (const uint32_t*)(Bs + s * GBUF);

        uint4 br[4];
#pragma unroll
        for (int nt = 0; nt < 4; nt++)
            br[nt] = *(const uint4*)&Bb[(wn + nt * 8 + g) * 16 + cB[nt]];

#pragma unroll
        for (int mt = 0; mt < 4; mt++) {
            const int r0 = wm + mt * 16 + g;
            uint4 ar0 = *(const uint4*)&Ab[r0 * 16 + cA0];
            uint4 ar1 = *(const uint4*)&Ab[(r0 + 8) * 16 + cA8];
#pragma unroll
            for (int nt = 0; nt < 4; nt++) {
                mma8v(acc[mt][nt], ar0.x, ar1.x, ar0.y, ar1.y, br[nt].x, br[nt].y);
                mma8v(acc[mt][nt], ar0.z, ar1.z, ar0.w, ar1.w, br[nt].z, br[nt].w);
            }
        }

        if (more) {
            uint32_t* dA = stA + (s ^ 1) * GBUF;
            uint32_t* dB = stB + (s ^ 1) * GBUF;
            float av[8] = {pa0.x, pa0.y, pa0.z, pa0.w, pa1.x, pa1.y, pa1.z, pa1.w};
            float bv[8] = {pb0.x, pb0.y, pb0.z, pb0.w, pb1.x, pb1.y, pb1.z, pb1.w};
#pragma unroll
            for (int i = 0; i < 8; i++) {
                uint32_t ua, ub;
                CVT_TF32(ua, av[i]); CVT_TF32(ub, bv[i]);
                dA[col[i]] = ua; dB[col[i]] = ub;
            }
            __syncthreads();
        }
    }

    // ---- epilogue: direct fragment stores ----
#pragma unroll
    for (int mt = 0; mt < 4; mt++) {
#pragma unroll
        for (int nt = 0; nt < 4; nt++) {
            int gcol = bn + wn + nt * 8 + 2 * t;
            float2 bv = *(const float2*)&bias[gcol];
            int r0 = bm + wm + mt * 16 + g;
#pragma unroll
            for (int hrow = 0; hrow < 2; hrow++) {
                size_t gidx = (size_t)(r0 + hrow * 8) * N + gcol;
                float c0 = acc[mt][nt][2 * hrow]     + bv.x;
                float c1 = acc[mt][nt][2 * hrow + 1] + bv.y;
                if (EPI == 1) {
                    float2 rv = *(const float2*)&res[gidx];
                    c0 += rv.x; c1 += rv.y;
                }
                if (EPI == 2) {
                    c0 = c0 / (1.f + __expf(-1.702f * c0));
                    c1 = c1 / (1.f + __expf(-1.702f * c1));
                }
                *(float2*)&C[gidx] = make_float2(c0, c1);
            }
        }
    }
}

// ---------------- Flash attention via mma.sync tf32 (R6, unchanged) ----------------
#define KS_STR 68
#define VS_STR 72
#define PS_STR 68
#define ATT_SMEM ((64 * KS_STR + 64 * VS_STR + 4 * 16 * PS_STR) * 4)

__global__ __launch_bounds__(128) void attn_mma(const float* __restrict__ qkv,
                                                float* __restrict__ o)
{
    extern __shared__ float asmem[];
    float* Ks = asmem;
    float* Vs = asmem + 64 * KS_STR;
    float* Ps = asmem + 64 * KS_STR + 64 * VS_STR;

    const int tid  = threadIdx.x;
    const int w    = tid >> 5;
    const int lane = tid & 31;
    const int g = lane >> 2, t = lane & 3;
    const int qb = blockIdx.x * 64 + w * 16;
    const int h = blockIdx.y, n = blockIdx.z;

    const float qscale = 0.125f * 1.44269504088896f;

    uint32_t aq[8][4];
    {
        size_t r0 = ((size_t)(qb + g) * NB + n) * E3 + h * DH;
        size_t r1 = ((size_t)(qb + g + 8) * NB + n) * E3 + h * DH;
#pragma unroll
        for (int ch = 0; ch < 8; ch++) {
            float v0 = qkv[r0 + ch * 8 + t]     * qscale;
            float v1 = qkv[r1 + ch * 8 + t]     * qscale;
            float v2 = qkv[r0 + ch * 8 + t + 4] * qscale;
            float v3 = qkv[r1 + ch * 8 + t + 4] * qscale;
            CVT_TF32(aq[ch][0], v0); CVT_TF32(aq[ch][1], v1);
            CVT_TF32(aq[ch][2], v2); CVT_TF32(aq[ch][3], v3);
        }
    }

    float oc[8][4];
#pragma unroll
    for (int i = 0; i < 8; i++)
#pragma unroll
        for (int j = 0; j < 4; j++) oc[i][j] = 0.f;
    float m0 = -1e30f, m1 = -1e30f, l0 = 0.f, l1 = 0.f;

    const int srow  = tid >> 1;
    const int shalf = (tid & 1) * 32;

    for (int kb = 0; kb < L_SEQ / 64; kb++) {
        size_t kbase = ((size_t)(kb * 64 + srow) * NB + n) * E3 + EMB + h * DH + shalf;
        float4 kr[8];
#pragma unroll
        for (int i = 0; i < 8; i++) kr[i] = *(const float4*)&qkv[kbase + 4 * i];
        __syncthreads();
        {
            uint32_t* ks = (uint32_t*)&Ks[srow * KS_STR + shalf];
#pragma unroll
            for (int i = 0; i < 8; i++) {
                uint4 cv;
                CVT_TF32(cv.x, kr[i].x); CVT_TF32(cv.y, kr[i].y);
                CVT_TF32(cv.z, kr[i].z); CVT_TF32(cv.w, kr[i].w);
                *(uint4*)&ks[4 * i] = cv;
            }
        }
        size_t vbase = kbase + EMB;
#pragma unroll
        for (int i = 0; i < 8; i++) kr[i] = *(const float4*)&qkv[vbase + 4 * i];
        {
            uint32_t* vs = (uint32_t*)&Vs[srow * VS_STR + shalf];
#pragma unroll
            for (int i = 0; i < 8; i++) {
                uint4 cv;
                CVT_TF32(cv.x, kr[i].x); CVT_TF32(cv.y, kr[i].y);
                CVT_TF32(cv.z, kr[i].z); CVT_TF32(cv.w, kr[i].w);
                *(uint4*)&vs[4 * i] = cv;
            }
        }
        __syncthreads();

        float sc[8][4];
#pragma unroll
        for (int i = 0; i < 8; i++)
#pragma unroll
            for (int j = 0; j < 4; j++) sc[i][j] = 0.f;

        const uint32_t* ksb = (const uint32_t*)Ks;
#pragma unroll
        for (int nt = 0; nt < 8; nt++) {
#pragma unroll
            for (int ch = 0; ch < 8; ch++) {
                uint32_t b0 = ksb[(nt * 8 + g) * KS_STR + ch * 8 + t];
                uint32_t b1 = ksb[(nt * 8 + g) * KS_STR + ch * 8 + t + 4];
                mma8v(sc[nt], aq[ch][0], aq[ch][1], aq[ch][2], aq[ch][3], b0, b1);
            }
        }

        float tm0 = -1e30f, tm1 = -1e30f;
#pragma unroll
        for (int nt = 0; nt < 8; nt++) {
            tm0 = fmaxf(tm0, fmaxf(sc[nt][0], sc[nt][1]));
            tm1 = fmaxf(tm1, fmaxf(sc[nt][2], sc[nt][3]));
        }
        tm0 = fmaxf(tm0, __shfl_xor_sync(0xffffffffu, tm0, 1));
        tm0 = fmaxf(tm0, __shfl_xor_sync(0xffffffffu, tm0, 2));
        tm1 = fmaxf(tm1, __shfl_xor_sync(0xffffffffu, tm1, 1));
        tm1 = fmaxf(tm1, __shfl_xor_sync(0xffffffffu, tm1, 2));

        float nm0 = fmaxf(m0, tm0), nm1 = fmaxf(m1, tm1);
        float al0 = ex2f(m0 - nm0), al1 = ex2f(m1 - nm1);
        m0 = nm0; m1 = nm1;

        float s0 = 0.f, s1 = 0.f;
#pragma unroll
        for (int nt = 0; nt < 8; nt++) {
            sc[nt][0] = ex2f(sc[nt][0] - m0);
            sc[nt][1] = ex2f(sc[nt][1] - m0);
            sc[nt][2] = ex2f(sc[nt][2] - m1);
            sc[nt][3] = ex2f(sc[nt][3] - m1);
            s0 += sc[nt][0] + sc[nt][1];
            s1 += sc[nt][2] + sc[nt][3];
        }
        s0 += __shfl_xor_sync(0xffffffffu, s0, 1);
        s0 += __shfl_xor_sync(0xffffffffu, s0, 2);
        s1 += __shfl_xor_sync(0xffffffffu, s1, 1);
        s1 += __shfl_xor_sync(0xffffffffu, s1, 2);
        l0 = l0 * al0 + s0;
        l1 = l1 * al1 + s1;
#pragma unroll
        for (int nt = 0; nt < 8; nt++) {
            oc[nt][0] *= al0; oc[nt][1] *= al0;
            oc[nt][2] *= al1; oc[nt][3] *= al1;
        }

        uint32_t* pw = (uint32_t*)(Ps + w * 16 * PS_STR);
        __syncwarp();
#pragma unroll
        for (int nt = 0; nt < 8; nt++) {
            uint2 p0, p1;
            CVT_TF32(p0.x, sc[nt][0]); CVT_TF32(p0.y, sc[nt][1]);
            CVT_TF32(p1.x, sc[nt][2]); CVT_TF32(p1.y, sc[nt][3]);
            *(uint2*)&pw[g * PS_STR + nt * 8 + 2 * t]       = p0;
            *(uint2*)&pw[(g + 8) * PS_STR + nt * 8 + 2 * t] = p1;
        }
        __syncwarp();

        const uint32_t* vsb = (const uint32_t*)Vs;
#pragma unroll
        for (int ch = 0; ch < 8; ch++) {
            uint32_t ap0 = pw[g * PS_STR + ch * 8 + t];
            uint32_t ap1 = pw[(g + 8) * PS_STR + ch * 8 + t];
            uint32_t ap2 = pw[g * PS_STR + ch * 8 + t + 4];
            uint32_t ap3 = pw[(g + 8) * PS_STR + ch * 8 + t + 4];
#pragma unroll
            for (int nt = 0; nt < 8; nt++) {
                uint32_t b0 = vsb[(ch * 8 + t) * VS_STR + nt * 8 + g];
                uint32_t b1 = vsb[(ch * 8 + t + 4) * VS_STR + nt * 8 + g];
                mma8v(oc[nt], ap0, ap1, ap2, ap3, b0, b1);
            }
        }
    }

    float i0 = 1.f / l0, i1 = 1.f / l1;
    size_t o0 = ((size_t)(qb + g) * NB + n) * EMB + h * DH;
    size_t o1 = ((size_t)(qb + g + 8) * NB + n) * EMB + h * DH;
#pragma unroll
    for (int nt = 0; nt < 8; nt++) {
        *(float2*)&o[o0 + nt * 8 + 2 * t] = make_float2(oc[nt][0] * i0, oc[nt][1] * i0);
        *(float2*)&o[o1 + nt * 8 + 2 * t] = make_float2(oc[nt][2] * i1, oc[nt][3] * i1);
    }
}

// ---------------- launch ----------------
extern "C" void kernel_launch(void* const* d_in, const int* in_sizes, int n_in,
                              void* d_out, int out_size)
{
    const float* x      = (const float*)d_in[0];
    const float* ln1_w  = (const float*)d_in[1];
    const float* ln1_b  = (const float*)d_in[2];
    const float* w_qkv  = (const float*)d_in[3];
    const float* b_qkv  = (const float*)d_in[4];
    const float* w_out  = (const float*)d_in[5];
    const float* b_out  = (const float*)d_in[6];
    const float* ln2_w  = (const float*)d_in[7];
    const float* ln2_b  = (const float*)d_in[8];
    const float* w_fc   = (const float*)d_in[9];
    const float* b_fc   = (const float*)d_in[10];
    const float* w_proj = (const float*)d_in[11];
    const float* b_proj = (const float*)d_in[12];
    float* out = (float*)d_out;

    float *h, *qkv, *attn, *x1, *f;
    cudaGetSymbolAddress((void**)&h,    g_h);
    cudaGetSymbolAddress((void**)&qkv,  g_qkv);
    cudaGetSymbolAddress((void**)&attn, g_attn);
    cudaGetSymbolAddress((void**)&x1,   g_x1);
    cudaGetSymbolAddress((void**)&f,    g_f);

    cudaFuncSetAttribute(gemm_mma<0>, cudaFuncAttributeMaxDynamicSharedMemorySize, GT_SMEM);
    cudaFuncSetAttribute(gemm_mma<1>, cudaFuncAttributeMaxDynamicSharedMemorySize, GT_SMEM);
    cudaFuncSetAttribute(gemm_mma<2>, cudaFuncAttributeMaxDynamicSharedMemorySize, GT_SMEM);
    cudaFuncSetAttribute(attn_mma,    cudaFuncAttributeMaxDynamicSharedMemorySize, ATT_SMEM);

    ln_kernel<<<ROWS, 256>>>(x, ln1_w, ln1_b, h);
    gemm_mma<0><<<dim3(E3 / 128, ROWS / 128), 256, GT_SMEM>>>(h, w_qkv, b_qkv, nullptr, qkv,
                                                              ROWS, E3, EMB);
    attn_mma<<<dim3(L_SEQ / 64, NHEAD, NB), 128, ATT_SMEM>>>(qkv, attn);
    gemm_mma<1><<<dim3(EMB / 128, ROWS / 128), 256, GT_SMEM>>>(attn, w_out, b_out, x, x1,
                                                               ROWS, EMB, EMB);
    ln_kernel<<<ROWS, 256>>>(x1, ln2_w, ln2_b, h);
    gemm_mma<2><<<dim3(E4 / 128, ROWS / 128), 256, GT_SMEM>>>(h, w_fc, b_fc, nullptr, f,
                                                              ROWS, E4, EMB);
    gemm_mma<1><<<dim3(EMB / 128, ROWS / 128), 256, GT_SMEM>>>(f, w_proj, b_proj, x1, out,
                                                               ROWS, EMB, E4);
}

// round 9
// speedup vs baseline: 1.8946x; 1.2019x over previous
#include <cuda_runtime.h>
#include <math.h>
#include <stdint.h>

#define L_SEQ  2048
#define NB     4
#define EMB    768
#define NHEAD  12
#define DH     64
#define ROWS   (L_SEQ * NB)      // 8192
#define E3     (3 * EMB)         // 2304
#define E4     (4 * EMB)         // 3072

// ---------------- scratch ----------------
__device__ float g_h   [ (size_t)ROWS * EMB ];   // LN out, tf32+permuted
__device__ float g_qkv [ (size_t)ROWS * E3  ];   // normal layout
__device__ float g_attn[ (size_t)ROWS * EMB ];   // tf32+permuted
__device__ float g_x1  [ (size_t)ROWS * EMB ];   // normal
__device__ float g_f   [ (size_t)ROWS * E4  ];   // tf32+permuted
__device__ float g_wqkv [ (size_t)E3  * EMB ];   // permuted weights
__device__ float g_wout [ (size_t)EMB * EMB ];
__device__ float g_wfc  [ (size_t)E4  * EMB ];
__device__ float g_wproj[ (size_t)EMB * E4  ];

#define CVT_TF32(d, s) asm volatile("cvt.rna.tf32.f32 %0, %1;" : "=r"(d) : "f"(s))

__device__ __forceinline__ uint32_t smem_u32(const void* p) {
    uint32_t a;
    asm("{ .reg .u64 t; cvta.to.shared.u64 t, %1; cvt.u32.u64 %0, t; }" : "=r"(a) : "l"(p));
    return a;
}
__device__ __forceinline__ void cp16(uint32_t dst, const void* src) {
    asm volatile("cp.async.cg.shared.global [%0], [%1], 16;" :: "r"(dst), "l"(src));
}
#define CP_COMMIT() asm volatile("cp.async.commit_group;" ::: "memory")
#define CP_WAIT(n)  asm volatile("cp.async.wait_group %0;" :: "n"(n) : "memory")

__device__ __forceinline__ float ex2f(float x) {
    float y; asm("ex2.approx.f32 %0, %1;" : "=f"(y) : "f"(x)); return y;
}
__device__ __forceinline__ void mma8v(float* c,
                                      uint32_t a0, uint32_t a1, uint32_t a2, uint32_t a3,
                                      uint32_t b0, uint32_t b1) {
    asm volatile(
        "mma.sync.aligned.m16n8k8.row.col.f32.tf32.tf32.f32 "
        "{%0,%1,%2,%3}, {%4,%5,%6,%7}, {%8,%9}, {%0,%1,%2,%3};"
        : "+f"(c[0]), "+f"(c[1]), "+f"(c[2]), "+f"(c[3])
        : "r"(a0), "r"(a1), "r"(a2), "r"(a3), "r"(b0), "r"(b1));
}

// ---------------- weight permute + tf32 round (per-launch pre-pass) ----------------
// out[row][16*blk + perm(j)] = tf32(in[row][16*blk + j]), perm(j) = (j&3)*4 + (j>>2)
__global__ __launch_bounds__(256) void permute_w(const float* __restrict__ in,
                                                 float* __restrict__ out, int total)
{
    int i = blockIdx.x * 256 + threadIdx.x;
    if (i < total) {
        int j  = i & 15;
        int pj = ((j & 3) << 2) | (j >> 2);
        uint32_t v; CVT_TF32(v, in[i]);
        ((uint32_t*)out)[(i & ~15) | pj] = v;
    }
}

// ---------------- LayerNorm -> tf32 + permuted output ----------------
__global__ __launch_bounds__(256) void ln_kernel(const float* __restrict__ x,
                                                 const float* __restrict__ w,
                                                 const float* __restrict__ b,
                                                 float* __restrict__ out)
{
    int row = blockIdx.x;
    const float* xr = x + (size_t)row * EMB;
    uint32_t* orow = (uint32_t*)(out + (size_t)row * EMB);
    int t = threadIdx.x;

    float v[3];
    float sum = 0.f, sq = 0.f;
#pragma unroll
    for (int i = 0; i < 3; i++) {
        v[i] = xr[t + 256 * i];
        sum += v[i];
        sq  += v[i] * v[i];
    }
    __shared__ float s1[8], s2[8], bc[2];
    for (int o = 16; o > 0; o >>= 1) {
        sum += __shfl_xor_sync(0xffffffffu, sum, o);
        sq  += __shfl_xor_sync(0xffffffffu, sq,  o);
    }
    int wid = t >> 5, lid = t & 31;
    if (lid == 0) { s1[wid] = sum; s2[wid] = sq; }
    __syncthreads();
    if (t == 0) {
        float ts = 0.f, tq = 0.f;
#pragma unroll
        for (int i = 0; i < 8; i++) { ts += s1[i]; tq += s2[i]; }
        float mu  = ts * (1.0f / EMB);
        float var = tq * (1.0f / EMB) - mu * mu;
        bc[0] = mu;
        bc[1] = rsqrtf(var + 1e-5f);
    }
    __syncthreads();
    float mu = bc[0], rstd = bc[1];
    int j  = t & 15;
    int pj = ((j & 3) << 2) | (j >> 2);
#pragma unroll
    for (int i = 0; i < 3; i++) {
        int c = t + 256 * i;
        float y = (v[i] - mu) * rstd * w[c] + b[c];
        uint32_t u; CVT_TF32(u, y);
        orow[(c & ~15) | pj] = u;
    }
}

// ---------------- cp.async tf32 GEMM: C = A[M,K] @ B[N,K]^T + bias (+EPI) ----------------
// A, B pre-rounded to tf32 and k-permuted in gmem. 128x128x16 tile, 256 thr,
// 8 warps 2x4, 3-stage cp.async pipeline, XOR-swizzled smem, LDS.128 frag reads.
// EPI 0: plain  1: +res  2: QuickGELU with permuted output
#define GS 3
#define GBUF (128 * 16)                     // floats per operand stage (8KB)
#define GT_SMEM (GS * 2 * GBUF * 4)         // 49152 bytes

template <int EPI>
__global__ __launch_bounds__(256, 2) void gemm_cp(
    const float* __restrict__ A, const float* __restrict__ B,
    const float* __restrict__ bias, const float* __restrict__ res,
    float* __restrict__ C, int M, int N, int K)
{
    extern __shared__ float smem[];
    const uint32_t sb = smem_u32(smem);

    const int tid  = threadIdx.x;
    const int wid  = tid >> 5;
    const int lane = tid & 31;
    const int g = lane >> 2, t = lane & 3;

    const int bm = blockIdx.y * 128;
    const int bn = blockIdx.x * 128;
    const int wm = (wid >> 2) * 64;
    const int wn = (wid & 3) * 32;

    // ---- staging: 2 x 16B of A + 2 x 16B of B per thread per chunk ----
    const int lr = tid >> 1;                 // row 0..127
    const int hc = (tid & 1) * 2;            // 16B-chunk pair: hc, hc+1
    const int sw = ((lr & 3) ^ ((lr >> 2) & 3)) << 2;
    const float* Ap = A + (size_t)(bm + lr) * K + hc * 4;
    const float* Bp = B + (size_t)(bn + lr) * K + hc * 4;
    const uint32_t dA0 = sb + (lr * 16 + ((4 * hc)     ^ sw)) * 4;
    const uint32_t dA1 = sb + (lr * 16 + ((4 * hc + 4) ^ sw)) * 4;
    const uint32_t dB0 = dA0 + GS * GBUF * 4;
    const uint32_t dB1 = dA1 + GS * GBUF * 4;

    // ---- fragment read columns ----
    const int cA0 = (4 * t) ^ (((g & 3) ^ ((g >> 2) & 3)) << 2);
    const int cA8 = (4 * t) ^ (((g & 3) ^ (((g >> 2) + 2) & 3)) << 2);
    int cB[4];
#pragma unroll
    for (int nt = 0; nt < 4; nt++)
        cB[nt] = (4 * t) ^ (((g & 3) ^ (((g >> 2) + 2 * nt) & 3)) << 2);

    float acc[4][4][4];
#pragma unroll
    for (int i = 0; i < 4; i++)
#pragma unroll
        for (int j = 0; j < 4; j++)
#pragma unroll
            for (int q = 0; q < 4; q++) acc[i][j][q] = 0.f;

    const int NC = K / 16;

    // preload stages for chunks 0..GS-2
#pragma unroll
    for (int c = 0; c < GS - 1; c++) {
        uint32_t so = (uint32_t)(c * GBUF * 4);
        const float* a = Ap + c * 16;
        const float* b = Bp + c * 16;
        cp16(dA0 + so, a);
        cp16(dA1 + so, a + 4);
        cp16(dB0 + so, b);
        cp16(dB1 + so, b + 4);
        CP_COMMIT();
    }

    for (int c = 0; c < NC; c++) {
        CP_WAIT(GS - 2);           // chunk c landed
        __syncthreads();           // visible to all; buffer (c-1)%GS free

        int nc = c + GS - 1;
        if (nc < NC) {
            uint32_t so = (uint32_t)((nc % GS) * GBUF * 4);
            const float* a = Ap + nc * 16;
            const float* b = Bp + nc * 16;
            cp16(dA0 + so, a);
            cp16(dA1 + so, a + 4);
            cp16(dB0 + so, b);
            cp16(dB1 + so, b + 4);
        }
        CP_COMMIT();               // keep group count in lockstep

        const int s = c % GS;
        const uint32_t* Ab = (const uint32_t*)(smem + s * GBUF);
        const uint32_t* Bb = (const uint32_t*)(smem + (GS + s) * GBUF);

        uint4 br[4];
#pragma unroll
        for (int nt = 0; nt < 4; nt++)
            br[nt] = *(const uint4*)&Bb[(wn + nt * 8 + g) * 16 + cB[nt]];

#pragma unroll
        for (int mt = 0; mt < 4; mt++) {
            const int r0 = wm + mt * 16 + g;
            uint4 ar0 = *(const uint4*)&Ab[r0 * 16 + cA0];
            uint4 ar1 = *(const uint4*)&Ab[(r0 + 8) * 16 + cA8];
#pragma unroll
            for (int nt = 0; nt < 4; nt++) {
                mma8v(acc[mt][nt], ar0.x, ar1.x, ar0.y, ar1.y, br[nt].x, br[nt].y);
                mma8v(acc[mt][nt], ar0.z, ar1.z, ar0.w, ar1.w, br[nt].z, br[nt].w);
            }
        }
    }

    // ---- epilogue ----
#pragma unroll
    for (int mt = 0; mt < 4; mt++) {
#pragma unroll
        for (int nt = 0; nt < 4; nt++) {
            int gcol = bn + wn + nt * 8 + 2 * t;
            float2 bv = *(const float2*)&bias[gcol];
            int r0 = bm + wm + mt * 16 + g;
#pragma unroll
            for (int hrow = 0; hrow < 2; hrow++) {
                int grow = r0 + hrow * 8;
                float c0 = acc[mt][nt][2 * hrow]     + bv.x;
                float c1 = acc[mt][nt][2 * hrow + 1] + bv.y;
                if (EPI == 1) {
                    size_t gidx = (size_t)grow * N + gcol;
                    float2 rv = *(const float2*)&res[gidx];
                    c0 += rv.x; c1 += rv.y;
                    *(float2*)&C[gidx] = make_float2(c0, c1);
                } else if (EPI == 0) {
                    size_t gidx = (size_t)grow * N + gcol;
                    *(float2*)&C[gidx] = make_float2(c0, c1);
                } else {             // QuickGELU -> tf32 + permuted
                    c0 = c0 / (1.f + __expf(-1.702f * c0));
                    c1 = c1 / (1.f + __expf(-1.702f * c1));
                    int p  = gcol & 15;
                    int pp = ((p & 3) << 2) | (p >> 2);
                    size_t b16 = (size_t)grow * N + (gcol & ~15);
                    uint32_t u0, u1;
                    CVT_TF32(u0, c0); CVT_TF32(u1, c1);
                    ((uint32_t*)C)[b16 + pp]     = u0;
                    ((uint32_t*)C)[b16 + pp + 4] = u1;   // perm(p+1) = perm(p)+4 (p even)
                }
            }
        }
    }
}

// ---------------- Flash attention via mma.sync tf32; permuted tf32 output ----------------
#define KS_STR 68
#define VS_STR 72
#define PS_STR 68
#define ATT_SMEM ((64 * KS_STR + 64 * VS_STR + 4 * 16 * PS_STR) * 4)

__global__ __launch_bounds__(128) void attn_mma(const float* __restrict__ qkv,
                                                float* __restrict__ o)
{
    extern __shared__ float asmem[];
    float* Ks = asmem;
    float* Vs = asmem + 64 * KS_STR;
    float* Ps = asmem + 64 * KS_STR + 64 * VS_STR;

    const int tid  = threadIdx.x;
    const int w    = tid >> 5;
    const int lane = tid & 31;
    const int g = lane >> 2, t = lane & 3;
    const int qb = blockIdx.x * 64 + w * 16;
    const int h = blockIdx.y, n = blockIdx.z;

    const float qscale = 0.125f * 1.44269504088896f;

    uint32_t aq[8][4];
    {
        size_t r0 = ((size_t)(qb + g) * NB + n) * E3 + h * DH;
        size_t r1 = ((size_t)(qb + g + 8) * NB + n) * E3 + h * DH;
#pragma unroll
        for (int ch = 0; ch < 8; ch++) {
            float v0 = qkv[r0 + ch * 8 + t]     * qscale;
            float v1 = qkv[r1 + ch * 8 + t]     * qscale;
            float v2 = qkv[r0 + ch * 8 + t + 4] * qscale;
            float v3 = qkv[r1 + ch * 8 + t + 4] * qscale;
            CVT_TF32(aq[ch][0], v0); CVT_TF32(aq[ch][1], v1);
            CVT_TF32(aq[ch][2], v2); CVT_TF32(aq[ch][3], v3);
        }
    }

    float oc[8][4];
#pragma unroll
    for (int i = 0; i < 8; i++)
#pragma unroll
        for (int j = 0; j < 4; j++) oc[i][j] = 0.f;
    float m0 = -1e30f, m1 = -1e30f, l0 = 0.f, l1 = 0.f;

    const int srow  = tid >> 1;
    const int shalf = (tid & 1) * 32;

    for (int kb = 0; kb < L_SEQ / 64; kb++) {
        size_t kbase = ((size_t)(kb * 64 + srow) * NB + n) * E3 + EMB + h * DH + shalf;
        float4 kr[8];
#pragma unroll
        for (int i = 0; i < 8; i++) kr[i] = *(const float4*)&qkv[kbase + 4 * i];
        __syncthreads();
        {
            uint32_t* ks = (uint32_t*)&Ks[srow * KS_STR + shalf];
#pragma unroll
            for (int i = 0; i < 8; i++) {
                uint4 cv;
                CVT_TF32(cv.x, kr[i].x); CVT_TF32(cv.y, kr[i].y);
                CVT_TF32(cv.z, kr[i].z); CVT_TF32(cv.w, kr[i].w);
                *(uint4*)&ks[4 * i] = cv;
            }
        }
        size_t vbase = kbase + EMB;
#pragma unroll
        for (int i = 0; i < 8; i++) kr[i] = *(const float4*)&qkv[vbase + 4 * i];
        {
            uint32_t* vs = (uint32_t*)&Vs[srow * VS_STR + shalf];
#pragma unroll
            for (int i = 0; i < 8; i++) {
                uint4 cv;
                CVT_TF32(cv.x, kr[i].x); CVT_TF32(cv.y, kr[i].y);
                CVT_TF32(cv.z, kr[i].z); CVT_TF32(cv.w, kr[i].w);
                *(uint4*)&vs[4 * i] = cv;
            }
        }
        __syncthreads();

        float sc[8][4];
#pragma unroll
        for (int i = 0; i < 8; i++)
#pragma unroll
            for (int j = 0; j < 4; j++) sc[i][j] = 0.f;

        const uint32_t* ksb = (const uint32_t*)Ks;
#pragma unroll
        for (int nt = 0; nt < 8; nt++) {
#pragma unroll
            for (int ch = 0; ch < 8; ch++) {
                uint32_t b0 = ksb[(nt * 8 + g) * KS_STR + ch * 8 + t];
                uint32_t b1 = ksb[(nt * 8 + g) * KS_STR + ch * 8 + t + 4];
                mma8v(sc[nt], aq[ch][0], aq[ch][1], aq[ch][2], aq[ch][3], b0, b1);
            }
        }

        float tm0 = -1e30f, tm1 = -1e30f;
#pragma unroll
        for (int nt = 0; nt < 8; nt++) {
            tm0 = fmaxf(tm0, fmaxf(sc[nt][0], sc[nt][1]));
            tm1 = fmaxf(tm1, fmaxf(sc[nt][2], sc[nt][3]));
        }
        tm0 = fmaxf(tm0, __shfl_xor_sync(0xffffffffu, tm0, 1));
        tm0 = fmaxf(tm0, __shfl_xor_sync(0xffffffffu, tm0, 2));
        tm1 = fmaxf(tm1, __shfl_xor_sync(0xffffffffu, tm1, 1));
        tm1 = fmaxf(tm1, __shfl_xor_sync(0xffffffffu, tm1, 2));

        float nm0 = fmaxf(m0, tm0), nm1 = fmaxf(m1, tm1);
        float al0 = ex2f(m0 - nm0), al1 = ex2f(m1 - nm1);
        m0 = nm0; m1 = nm1;

        float s0 = 0.f, s1 = 0.f;
#pragma unroll
        for (int nt = 0; nt < 8; nt++) {
            sc[nt][0] = ex2f(sc[nt][0] - m0);
            sc[nt][1] = ex2f(sc[nt][1] - m0);
            sc[nt][2] = ex2f(sc[nt][2] - m1);
            sc[nt][3] = ex2f(sc[nt][3] - m1);
            s0 += sc[nt][0] + sc[nt][1];
            s1 += sc[nt][2] + sc[nt][3];
        }
        s0 += __shfl_xor_sync(0xffffffffu, s0, 1);
        s0 += __shfl_xor_sync(0xffffffffu, s0, 2);
        s1 += __shfl_xor_sync(0xffffffffu, s1, 1);
        s1 += __shfl_xor_sync(0xffffffffu, s1, 2);
        l0 = l0 * al0 + s0;
        l1 = l1 * al1 + s1;
#pragma unroll
        for (int nt = 0; nt < 8; nt++) {
            oc[nt][0] *= al0; oc[nt][1] *= al0;
            oc[nt][2] *= al1; oc[nt][3] *= al1;
        }

        uint32_t* pw = (uint32_t*)(Ps + w * 16 * PS_STR);
        __syncwarp();
#pragma unroll
        for (int nt = 0; nt < 8; nt++) {
            uint2 p0, p1;
            CVT_TF32(p0.x, sc[nt][0]); CVT_TF32(p0.y, sc[nt][1]);
            CVT_TF32(p1.x, sc[nt][2]); CVT_TF32(p1.y, sc[nt][3]);
            *(uint2*)&pw[g * PS_STR + nt * 8 + 2 * t]       = p0;
            *(uint2*)&pw[(g + 8) * PS_STR + nt * 8 + 2 * t] = p1;
        }
        __syncwarp();

        const uint32_t* vsb = (const uint32_t*)Vs;
#pragma unroll
        for (int ch = 0; ch < 8; ch++) {
            uint32_t ap0 = pw[g * PS_STR + ch * 8 + t];
            uint32_t ap1 = pw[(g + 8) * PS_STR + ch * 8 + t];
            uint32_t ap2 = pw[g * PS_STR + ch * 8 + t + 4];
            uint32_t ap3 = pw[(g + 8) * PS_STR + ch * 8 + t + 4];
#pragma unroll
            for (int nt = 0; nt < 8; nt++) {
                uint32_t b0 = vsb[(ch * 8 + t) * VS_STR + nt * 8 + g];
                uint32_t b1 = vsb[(ch * 8 + t + 4) * VS_STR + nt * 8 + g];
                mma8v(oc[nt], ap0, ap1, ap2, ap3, b0, b1);
            }
        }
    }

    // epilogue: tf32-rounded, k-permuted stores (feeds gemm_cp as A operand)
    float i0 = 1.f / l0, i1 = 1.f / l1;
    size_t o0 = ((size_t)(qb + g) * NB + n) * EMB + h * DH;
    size_t o1 = ((size_t)(qb + g + 8) * NB + n) * EMB + h * DH;
#pragma unroll
    for (int nt = 0; nt < 8; nt++) {
        int d  = nt * 8 + 2 * t;
        int p  = d & 15;
        int pp = ((p & 3) << 2) | (p >> 2);
        int b16 = d & ~15;
        uint32_t u0, u1, u2, u3;
        CVT_TF32(u0, oc[nt][0] * i0); CVT_TF32(u1, oc[nt][1] * i0);
        CVT_TF32(u2, oc[nt][2] * i1); CVT_TF32(u3, oc[nt][3] * i1);
        ((uint32_t*)o)[o0 + b16 + pp]     = u0;
        ((uint32_t*)o)[o0 + b16 + pp + 4] = u1;
        ((uint32_t*)o)[o1 + b16 + pp]     = u2;
        ((uint32_t*)o)[o1 + b16 + pp + 4] = u3;
    }
}

// ---------------- launch ----------------
extern "C" void kernel_launch(void* const* d_in, const int* in_sizes, int n_in,
                              void* d_out, int out_size)
{
    const float* x      = (const float*)d_in[0];
    const float* ln1_w  = (const float*)d_in[1];
    const float* ln1_b  = (const float*)d_in[2];
    const float* w_qkv  = (const float*)d_in[3];
    const float* b_qkv  = (const float*)d_in[4];
    const float* w_out  = (const float*)d_in[5];
    const float* b_out  = (const float*)d_in[6];
    const float* ln2_w  = (const float*)d_in[7];
    const float* ln2_b  = (const float*)d_in[8];
    const float* w_fc   = (const float*)d_in[9];
    const float* b_fc   = (const float*)d_in[10];
    const float* w_proj = (const float*)d_in[11];
    const float* b_proj = (const float*)d_in[12];
    float* out = (float*)d_out;

    float *h, *qkv, *attn, *x1, *f, *wqkv, *wout, *wfc, *wproj;
    cudaGetSymbolAddress((void**)&h,     g_h);
    cudaGetSymbolAddress((void**)&qkv,   g_qkv);
    cudaGetSymbolAddress((void**)&attn,  g_attn);
    cudaGetSymbolAddress((void**)&x1,    g_x1);
    cudaGetSymbolAddress((void**)&f,     g_f);
    cudaGetSymbolAddress((void**)&wqkv,  g_wqkv);
    cudaGetSymbolAddress((void**)&wout,  g_wout);
    cudaGetSymbolAddress((void**)&wfc,   g_wfc);
    cudaGetSymbolAddress((void**)&wproj, g_wproj);

    cudaFuncSetAttribute(gemm_cp<0>, cudaFuncAttributeMaxDynamicSharedMemorySize, GT_SMEM);
    cudaFuncSetAttribute(gemm_cp<1>, cudaFuncAttributeMaxDynamicSharedMemorySize, GT_SMEM);
    cudaFuncSetAttribute(gemm_cp<2>, cudaFuncAttributeMaxDynamicSharedMemorySize, GT_SMEM);
    cudaFuncSetAttribute(attn_mma,   cudaFuncAttributeMaxDynamicSharedMemorySize, ATT_SMEM);

    // weight pre-pass: tf32 round + k-permute
    permute_w<<<(E3 * EMB + 255) / 256, 256>>>(w_qkv, wqkv, E3 * EMB);
    permute_w<<<(EMB * EMB + 255) / 256, 256>>>(w_out, wout, EMB * EMB);
    permute_w<<<(E4 * EMB + 255) / 256, 256>>>(w_fc, wfc, E4 * EMB);
    permute_w<<<(EMB * E4 + 255) / 256, 256>>>(w_proj, wproj, EMB * E4);

    ln_kernel<<<ROWS, 256>>>(x, ln1_w, ln1_b, h);
    gemm_cp<0><<<dim3(E3 / 128, ROWS / 128), 256, GT_SMEM>>>(h, wqkv, b_qkv, nullptr, qkv,
                                                             ROWS, E3, EMB);
    attn_mma<<<dim3(L_SEQ / 64, NHEAD, NB), 128, ATT_SMEM>>>(qkv, attn);
    gemm_cp<1><<<dim3(EMB / 128, ROWS / 128), 256, GT_SMEM>>>(attn, wout, b_out, x, x1,
                                                              ROWS, EMB, EMB);
    ln_kernel<<<ROWS, 256>>>(x1, ln2_w, ln2_b, h);
    gemm_cp<2><<<dim3(E4 / 128, ROWS / 128), 256, GT_SMEM>>>(h, wfc, b_fc, nullptr, f,
                                                             ROWS, E4, EMB);
    gemm_cp<1><<<dim3(EMB / 128, ROWS / 128), 256, GT_SMEM>>>(f, wproj, b_proj, x1, out,
                                                              ROWS, EMB, E4);
}